// round 1
// baseline (speedup 1.0000x reference)
#include <cuda_runtime.h>

#define NB   32
#define CIN  240
#define HH   56
#define WW   56
#define HW   3136
#define MID  120
#define COUT 480
#define GRP  3
#define GIN  80    // Cin / G
#define GMID 40    // mid / G
#define GOUT 160   // Cout / G

// Scratch (allocation-free rule: __device__ globals)
__device__ float g_y1[NB * MID * HW];   // conv1 output (post BN+ReLU)
__device__ float g_y2[NB * MID * HW];   // dw conv output, stored in SHUFFLED channel order

typedef unsigned long long u64;

static __device__ __forceinline__ u64 pack2(float lo, float hi) {
    u64 r; asm("mov.b64 %0, {%1, %2};" : "=l"(r) : "f"(lo), "f"(hi)); return r;
}
static __device__ __forceinline__ void ffma2(u64& d, u64 a, u64 b) {
    asm("fma.rn.f32x2 %0, %1, %2, %3;" : "=l"(d) : "l"(a), "l"(b), "l"(d));
}

// ---------------------------------------------------------------------------
// K1: grouped 1x1 conv (groups=3) + BN + ReLU  ->  g_y1
// grid (49 pixel-tiles, 3 groups, 32 n), 256 threads
// CTA tile: 40 out-channels (one group) x 64 pixels, K=80
// ---------------------------------------------------------------------------
__global__ __launch_bounds__(256) void k1_conv1(
    const float* __restrict__ x, const float* __restrict__ w1,
    const float* __restrict__ scale1, const float* __restrict__ shift1)
{
    const int tile = blockIdx.x, g = blockIdx.y, n = blockIdx.z;
    const int tid = threadIdx.x, lane = tid & 31, warp = tid >> 5;

    __shared__ float xs[GIN][64];
    __shared__ float wt[GIN][GMID + 2];   // [k][m], pad 42 (stride%32=10 -> 2-way write conflict max)

    const float4* x4 = reinterpret_cast<const float4*>(
        x + ((size_t)n * CIN + g * GIN) * HW + tile * 64);
    for (int i = tid; i < GIN * 16; i += 256) {
        int c = i >> 4, q = i & 15;
        reinterpret_cast<float4*>(xs[c])[q] = x4[c * (HW / 4) + q];
    }
    for (int i = tid; i < GMID * GIN; i += 256) {
        int m = i / GIN, k = i - m * GIN;              // k fastest -> coalesced global read
        wt[k][m] = w1[(g * GMID + m) * GIN + k];
    }
    __syncthreads();

    float acc[5][2] = {};
    #pragma unroll 4
    for (int k = 0; k < GIN; k++) {
        float b0 = xs[k][lane], b1 = xs[k][lane + 32];
        #pragma unroll
        for (int i = 0; i < 5; i++) {
            float a = wt[k][warp * 5 + i];             // broadcast within warp
            acc[i][0] = fmaf(a, b0, acc[i][0]);
            acc[i][1] = fmaf(a, b1, acc[i][1]);
        }
    }

    float* yp = g_y1 + (size_t)n * MID * HW + tile * 64;
    #pragma unroll
    for (int i = 0; i < 5; i++) {
        int mg = g * GMID + warp * 5 + i;
        float s = scale1[mg], sh = shift1[mg];
        yp[(size_t)mg * HW + lane]      = fmaxf(fmaf(acc[i][0], s, sh), 0.f);
        yp[(size_t)mg * HW + lane + 32] = fmaxf(fmaf(acc[i][1], s, sh), 0.f);
    }
}

// ---------------------------------------------------------------------------
// K2: depthwise 3x3 (pad 1) + BN, writing in channel-shuffled order -> g_y2
// one thread per output element; grid = 12042240/256 blocks
// ---------------------------------------------------------------------------
__global__ __launch_bounds__(256) void k2_dw(
    const float* __restrict__ w2, const float* __restrict__ scale2,
    const float* __restrict__ shift2)
{
    int idx = blockIdx.x * 256 + threadIdx.x;          // exact cover, no guard needed
    int hw = idx % HW, nm = idx / HW;
    int m = nm % MID, n = nm / MID;
    int h = hw / WW, w = hw % WW;

    const float* yp = g_y1 + (size_t)nm * HW;
    const float* wp = w2 + m * 9;
    float acc = 0.f;
    #pragma unroll
    for (int dh = -1; dh <= 1; dh++) {
        int h2 = h + dh;
        if (h2 < 0 || h2 >= HH) continue;
        #pragma unroll
        for (int dw = -1; dw <= 1; dw++) {
            int w2i = w + dw;
            if (w2i < 0 || w2i >= WW) continue;
            acc = fmaf(wp[(dh + 1) * 3 + (dw + 1)], yp[h2 * WW + w2i], acc);
        }
    }
    float v = fmaf(acc, scale2[m], shift2[m]);
    // channel shuffle: old m=(i1*40+i2) -> new s=(i2*3+i1)
    int s = (m % GMID) * GRP + m / GMID;
    g_y2[((size_t)n * MID + s) * HW + hw] = v;
}

// ---------------------------------------------------------------------------
// K3 (dominant): fused grouped-1x1 conv3 + full 1x1 shortcut GEMM + epilogue
//   out = relu(BN3(conv3(y2_shuffled))) + BN_sc(wsc @ x)
// grid (49 pixel-tiles, 6 channel-tiles of 80, 32 n), 256 threads
// warps: wm = (tid>>5)&3 selects 20-row m-block, ph = tid>>7 selects pixel half.
// f32x2 packed FMAs: weights as m-pairs via LDS.128 m-quads, pixel broadcast-packed.
// ---------------------------------------------------------------------------
__global__ __launch_bounds__(256) void k3_fused(
    const float* __restrict__ x,
    const float* __restrict__ w3, const float* __restrict__ scale3,
    const float* __restrict__ shift3,
    const float* __restrict__ wsc, const float* __restrict__ scale_sc,
    const float* __restrict__ shift_sc,
    float* __restrict__ out)
{
    const int tile = blockIdx.x, ct = blockIdx.y, n = blockIdx.z;
    const int og  = ct * 80;
    const int grp = og / GOUT;
    const int tid = threadIdx.x, lane = tid & 31;
    const int wm = (tid >> 5) & 3;          // m-quarter: rows [wm*20, wm*20+20)
    const int ph = tid >> 7;                // pixel half
    const int pcol = ph * 32 + lane;

    // overlayed smem: phase A = xs[80][64] + wq[80][21] float4 (47360 B < 48K)
    //                 phase B = ys[40][64] + w3q[40][21] float4 (reuses same bytes)
    __shared__ __align__(16) char smem_raw[80 * 64 * 4 + 80 * 21 * 16];
    float  (*xs)[64]  = reinterpret_cast<float(*)[64]>(smem_raw);
    float4 (*wq)[21]  = reinterpret_cast<float4(*)[21]>(smem_raw + 80 * 64 * 4);
    float  (*ys)[64]  = xs;
    float4 (*w3q)[21] = reinterpret_cast<float4(*)[21]>(smem_raw + 40 * 64 * 4);

    u64 acc_sc[10], acc3[10];
    #pragma unroll
    for (int i = 0; i < 10; i++) { acc_sc[i] = 0ull; acc3[i] = 0ull; }

    // ---- shortcut GEMM: 80 out x 64 px x K=240 (3 chunks of 80) ----
    for (int kc = 0; kc < 3; kc++) {
        const float4* x4 = reinterpret_cast<const float4*>(
            x + ((size_t)n * CIN + kc * 80) * HW + tile * 64);
        for (int i = tid; i < 80 * 16; i += 256) {
            int c = i >> 4, q = i & 15;
            reinterpret_cast<float4*>(xs[c])[q] = x4[c * (HW / 4) + q];
        }
        // stage weights as m-quads: wq[k][mq] = {w[4mq..4mq+3][k]}
        const float* wbase = wsc + (size_t)og * CIN + kc * 80;
        for (int i = tid; i < 80 * 20; i += 256) {
            int k = i % 80, mq = i / 80;               // k fastest -> coalesced
            const float* wr = wbase + (size_t)(4 * mq) * CIN + k;
            float4 v;
            v.x = wr[0]; v.y = wr[CIN]; v.z = wr[2 * CIN]; v.w = wr[3 * CIN];
            wq[k][mq] = v;                             // stride 21 f4 -> conflict-free
        }
        __syncthreads();

        #pragma unroll 2
        for (int k = 0; k < 80; k++) {
            float p = xs[k][pcol];
            u64 b = pack2(p, p);
            #pragma unroll
            for (int j = 0; j < 5; j++) {
                ulonglong2 wv = *reinterpret_cast<const ulonglong2*>(&wq[k][wm * 5 + j]);
                ffma2(acc_sc[2 * j],     wv.x, b);     // m = wm*20+4j, +1
                ffma2(acc_sc[2 * j + 1], wv.y, b);     // m = wm*20+4j+2, +3
            }
        }
        __syncthreads();
    }

    // ---- conv3: 80 out x 64 px x K=40 (input already shuffled in g_y2) ----
    {
        const float4* y4 = reinterpret_cast<const float4*>(
            g_y2 + ((size_t)n * MID + grp * GMID) * HW + tile * 64);
        for (int i = tid; i < 40 * 16; i += 256) {
            int c = i >> 4, q = i & 15;
            reinterpret_cast<float4*>(ys[c])[q] = y4[c * (HW / 4) + q];
        }
        const float* w3base = w3 + (size_t)og * GMID;
        for (int i = tid; i < 40 * 20; i += 256) {
            int k = i % 40, mq = i / 40;
            const float* wr = w3base + (size_t)(4 * mq) * GMID + k;
            float4 v;
            v.x = wr[0]; v.y = wr[GMID]; v.z = wr[2 * GMID]; v.w = wr[3 * GMID];
            w3q[k][mq] = v;
        }
        __syncthreads();

        #pragma unroll 2
        for (int k = 0; k < 40; k++) {
            float p = ys[k][pcol];
            u64 b = pack2(p, p);
            #pragma unroll
            for (int j = 0; j < 5; j++) {
                ulonglong2 wv = *reinterpret_cast<const ulonglong2*>(&w3q[k][wm * 5 + j]);
                ffma2(acc3[2 * j],     wv.x, b);
                ffma2(acc3[2 * j + 1], wv.y, b);
            }
        }
    }

    // ---- epilogue: relu(BN3) + BN_sc ----
    float* op = out + (size_t)n * COUT * HW + tile * 64 + pcol;
    #pragma unroll
    for (int ip = 0; ip < 10; ip++) {
        int o = og + wm * 20 + 2 * ip;
        float2 v3 = *reinterpret_cast<float2*>(&acc3[ip]);
        float2 vs = *reinterpret_cast<float2*>(&acc_sc[ip]);
        float r0 = fmaxf(fmaf(v3.x, scale3[o],     shift3[o]),     0.f)
                 + fmaf(vs.x, scale_sc[o],     shift_sc[o]);
        float r1 = fmaxf(fmaf(v3.y, scale3[o + 1], shift3[o + 1]), 0.f)
                 + fmaf(vs.y, scale_sc[o + 1], shift_sc[o + 1]);
        op[(size_t)o * HW]       = r0;
        op[(size_t)(o + 1) * HW] = r1;
    }
}

// ---------------------------------------------------------------------------
extern "C" void kernel_launch(void* const* d_in, const int* in_sizes, int n_in,
                              void* d_out, int out_size)
{
    const float* x        = (const float*)d_in[0];
    const float* w1       = (const float*)d_in[1];
    const float* scale1   = (const float*)d_in[2];
    const float* shift1   = (const float*)d_in[3];
    const float* w2       = (const float*)d_in[4];
    const float* scale2   = (const float*)d_in[5];
    const float* shift2   = (const float*)d_in[6];
    const float* w3       = (const float*)d_in[7];
    const float* scale3   = (const float*)d_in[8];
    const float* shift3   = (const float*)d_in[9];
    const float* wsc      = (const float*)d_in[10];
    const float* scale_sc = (const float*)d_in[11];
    const float* shift_sc = (const float*)d_in[12];
    // d_in[13] = groups (constant 3, baked in)
    float* out = (float*)d_out;

    k1_conv1<<<dim3(49, 3, 32), 256>>>(x, w1, scale1, shift1);
    k2_dw<<<dim3((NB * MID * HW) / 256), 256>>>(w2, scale2, shift2);
    k3_fused<<<dim3(49, 6, 32), 256>>>(x, w3, scale3, shift3,
                                       wsc, scale_sc, shift_sc, out);
}

// round 2
// speedup vs baseline: 1.1440x; 1.1440x over previous
#include <cuda_runtime.h>

#define NB   32
#define CIN  240
#define HH   56
#define WW   56
#define HW   3136
#define MID  120
#define COUT 480
#define GRP  3
#define GIN  80    // Cin / G
#define GMID 40    // mid / G
#define GOUT 160   // Cout / G

// Scratch (allocation-free rule: __device__ globals)
__device__ float g_y1[NB * MID * HW];   // conv1 output (post BN+ReLU)
__device__ float g_y2[NB * MID * HW];   // dw conv output, SHUFFLED channel order
// Pre-packed tf32 A-fragments (mma.m16n8k8 per-lane layout)
// wsc: [ct(3)][kc(6)][kq(5)][mt(10)][lane(32)] -> 28800 uint4
// w3 : [ct(3)][kq(5)][mt(10)][lane(32)]        -> 4800 uint4
__device__ uint4 g_wscf[28800];
__device__ uint4 g_w3f[4800];

static __device__ __forceinline__ unsigned cvt_tf32(float f) {
    unsigned u; asm("cvt.rna.tf32.f32 %0, %1;" : "=r"(u) : "f"(f)); return u;
}

static __device__ __forceinline__ void mma_tf32(float c[4], const unsigned a[4],
                                                const unsigned b[2]) {
    asm volatile(
        "mma.sync.aligned.m16n8k8.row.col.f32.tf32.tf32.f32 "
        "{%0,%1,%2,%3}, {%4,%5,%6,%7}, {%8,%9}, {%0,%1,%2,%3};"
        : "+f"(c[0]), "+f"(c[1]), "+f"(c[2]), "+f"(c[3])
        : "r"(a[0]), "r"(a[1]), "r"(a[2]), "r"(a[3]), "r"(b[0]), "r"(b[1]));
}

// ---------------------------------------------------------------------------
// prep: repack wsc [480][240] and w3 [480][40] into per-lane tf32 fragments.
// A-frag for tile (row base rb, k base kb), lane l (gid=l>>2, tig=l&3):
//   a0=w[rb+gid][kb+tig] a1=w[rb+gid+8][kb+tig] a2=w[rb+gid][kb+tig+4] a3=w[rb+gid+8][kb+tig+4]
// ---------------------------------------------------------------------------
__global__ void prep_w(const float* __restrict__ wsc, const float* __restrict__ w3)
{
    int idx = blockIdx.x * 256 + threadIdx.x;
    if (idx < 28800) {
        int lane = idx & 31; int r = idx >> 5;
        int mt = r % 10; r /= 10;
        int kq = r % 5;  r /= 5;
        int kc = r % 6;  int ct = r / 6;
        int gid = lane >> 2, tig = lane & 3;
        int row = ct * GOUT + mt * 16 + gid;
        int col = kc * 40 + kq * 8 + tig;
        uint4 v;
        v.x = cvt_tf32(wsc[row * CIN + col]);
        v.y = cvt_tf32(wsc[(row + 8) * CIN + col]);
        v.z = cvt_tf32(wsc[row * CIN + col + 4]);
        v.w = cvt_tf32(wsc[(row + 8) * CIN + col + 4]);
        g_wscf[idx] = v;
    } else if (idx < 28800 + 4800) {
        int i2 = idx - 28800;
        int lane = i2 & 31; int r = i2 >> 5;
        int mt = r % 10; r /= 10;
        int kq = r % 5;  int ct = r / 5;
        int gid = lane >> 2, tig = lane & 3;
        int row = ct * GOUT + mt * 16 + gid;
        int col = kq * 8 + tig;
        uint4 v;
        v.x = cvt_tf32(w3[row * GMID + col]);
        v.y = cvt_tf32(w3[(row + 8) * GMID + col]);
        v.z = cvt_tf32(w3[row * GMID + col + 4]);
        v.w = cvt_tf32(w3[(row + 8) * GMID + col + 4]);
        g_w3f[i2] = v;
    }
}

// ---------------------------------------------------------------------------
// K1: grouped 1x1 conv + BN + ReLU -> g_y1   (fp32; LDS-pressure-reduced)
// grid (49, 3, 32), 256 thr. Warp: 10 m-rows x 32 px. Weights via broadcast LDS.
// ---------------------------------------------------------------------------
__global__ __launch_bounds__(256) void k1_conv1(
    const float* __restrict__ x, const float* __restrict__ w1,
    const float* __restrict__ scale1, const float* __restrict__ shift1)
{
    const int tile = blockIdx.x, g = blockIdx.y, n = blockIdx.z;
    const int tid = threadIdx.x, lane = tid & 31, warp = tid >> 5;
    const int wm4 = warp & 3;        // m block of 10
    const int wp  = warp >> 2;       // pixel half

    __shared__ float xs[GIN][64];
    __shared__ float wt2[GIN][48];   // per-k row: 4 blocks of 12 (10 used, 16B-aligned)

    const float4* x4 = reinterpret_cast<const float4*>(
        x + ((size_t)n * CIN + g * GIN) * HW + tile * 64);
    for (int i = tid; i < GIN * 16; i += 256) {
        int c = i >> 4, q = i & 15;
        reinterpret_cast<float4*>(xs[c])[q] = x4[c * (HW / 4) + q];
    }
    for (int i = tid; i < GIN * GMID; i += 256) {
        int k = i % GIN, mi = i / GIN;             // k fastest -> coalesced
        wt2[k][(mi / 10) * 12 + (mi % 10)] = w1[(g * GMID + mi) * GIN + k];
    }
    __syncthreads();

    float acc[10] = {};
    #pragma unroll 2
    for (int k = 0; k < GIN; k++) {
        float b = xs[k][wp * 32 + lane];
        const float* wr = &wt2[k][wm4 * 12];
        float4 wa = *reinterpret_cast<const float4*>(wr);
        float4 wb = *reinterpret_cast<const float4*>(wr + 4);
        float2 wc = *reinterpret_cast<const float2*>(wr + 8);
        acc[0] = fmaf(wa.x, b, acc[0]); acc[1] = fmaf(wa.y, b, acc[1]);
        acc[2] = fmaf(wa.z, b, acc[2]); acc[3] = fmaf(wa.w, b, acc[3]);
        acc[4] = fmaf(wb.x, b, acc[4]); acc[5] = fmaf(wb.y, b, acc[5]);
        acc[6] = fmaf(wb.z, b, acc[6]); acc[7] = fmaf(wb.w, b, acc[7]);
        acc[8] = fmaf(wc.x, b, acc[8]); acc[9] = fmaf(wc.y, b, acc[9]);
    }

    float* yp = g_y1 + (size_t)n * MID * HW + tile * 64 + wp * 32 + lane;
    #pragma unroll
    for (int j = 0; j < 10; j++) {
        int mg = g * GMID + wm4 * 10 + j;
        yp[(size_t)mg * HW] = fmaxf(fmaf(acc[j], scale1[mg], shift1[mg]), 0.f);
    }
}

// ---------------------------------------------------------------------------
// K2: depthwise 3x3 (pad 1) + BN, channel-shuffled write -> g_y2
// ---------------------------------------------------------------------------
__global__ __launch_bounds__(256) void k2_dw(
    const float* __restrict__ w2, const float* __restrict__ scale2,
    const float* __restrict__ shift2)
{
    int idx = blockIdx.x * 256 + threadIdx.x;
    int hw = idx % HW, nm = idx / HW;
    int m = nm % MID, n = nm / MID;
    int h = hw / WW, w = hw % WW;

    const float* yp = g_y1 + (size_t)nm * HW;
    const float* wp = w2 + m * 9;
    float acc = 0.f;
    #pragma unroll
    for (int dh = -1; dh <= 1; dh++) {
        int h2 = h + dh;
        if (h2 < 0 || h2 >= HH) continue;
        #pragma unroll
        for (int dw = -1; dw <= 1; dw++) {
            int w2i = w + dw;
            if (w2i < 0 || w2i >= WW) continue;
            acc = fmaf(wp[(dh + 1) * 3 + (dw + 1)], yp[h2 * WW + w2i], acc);
        }
    }
    float v = fmaf(acc, scale2[m], shift2[m]);
    int s = (m % GMID) * GRP + m / GMID;
    g_y2[((size_t)n * MID + s) * HW + hw] = v;
}

// ---------------------------------------------------------------------------
// K3: tf32 tensor-core fused conv3 + shortcut GEMM + epilogue
// CTA: M=160 (one exact output group), N=64 px. grid (49, 3, 32), 256 thr.
// Warp grid 2m x 4n: warp owns 5 m16-tiles x 2 n8-tiles. K chunked by 40.
// ---------------------------------------------------------------------------
__shared__ uint4    s_wf[1600];          // A frags for one K=40 chunk (25600 B)
__shared__ unsigned s_b0[5 * 8 * 33];    // B frag b0 (k=tig),   padded stride 33
__shared__ unsigned s_b1[5 * 8 * 33];    // B frag b1 (k=tig+4)

static __device__ __forceinline__ void stage_B(const float* __restrict__ src, int tid)
{
    const float4* s4 = reinterpret_cast<const float4*>(src);
    for (int i = tid; i < 640; i += 256) {
        int c = i >> 4, q = i & 15;                 // c: k-row 0..39, q: px quad
        float4 v = s4[c * (HW / 4) + q];
        int kq = c >> 3, tig = c & 3;
        unsigned* dst = ((c >> 2) & 1) ? s_b1 : s_b0;
        unsigned t0 = cvt_tf32(v.x), t1 = cvt_tf32(v.y),
                 t2 = cvt_tf32(v.z), t3 = cvt_tf32(v.w);
        int p0 = 4 * q;
        dst[(kq * 8 + ((p0    ) >> 3)) * 33 + ((p0    ) & 7) * 4 + tig] = t0;
        dst[(kq * 8 + ((p0 + 1) >> 3)) * 33 + ((p0 + 1) & 7) * 4 + tig] = t1;
        dst[(kq * 8 + ((p0 + 2) >> 3)) * 33 + ((p0 + 2) & 7) * 4 + tig] = t2;
        dst[(kq * 8 + ((p0 + 3) >> 3)) * 33 + ((p0 + 3) & 7) * 4 + tig] = t3;
    }
}

static __device__ __forceinline__ void compute_chunk(
    int wm, int wn, int lane, float acc[5][2][4])
{
    #pragma unroll
    for (int kq = 0; kq < 5; kq++) {
        unsigned a[5][4];
        #pragma unroll
        for (int j = 0; j < 5; j++)
            *reinterpret_cast<uint4*>(a[j]) = s_wf[(kq * 10 + wm * 5 + j) * 32 + lane];
        unsigned b[2][2];
        #pragma unroll
        for (int t = 0; t < 2; t++) {
            int bi = (kq * 8 + wn * 2 + t) * 33 + lane;
            b[t][0] = s_b0[bi];
            b[t][1] = s_b1[bi];
        }
        #pragma unroll
        for (int j = 0; j < 5; j++)
            #pragma unroll
            for (int t = 0; t < 2; t++)
                mma_tf32(acc[j][t], a[j], b[t]);
    }
}

__global__ __launch_bounds__(256) void k3_fused(
    const float* __restrict__ x,
    const float* __restrict__ scale3, const float* __restrict__ shift3,
    const float* __restrict__ scale_sc, const float* __restrict__ shift_sc,
    float* __restrict__ out)
{
    const int tile = blockIdx.x, ct = blockIdx.y, n = blockIdx.z;
    const int tid = threadIdx.x, lane = tid & 31, warp = tid >> 5;
    const int wm = warp & 1;           // m half (80 rows)
    const int wn = warp >> 1;          // 16-px strip
    const int gid = lane >> 2, tig = lane & 3;

    float acc_sc[5][2][4];
    float acc3[5][2][4];
    #pragma unroll
    for (int j = 0; j < 5; j++)
        #pragma unroll
        for (int t = 0; t < 2; t++)
            #pragma unroll
            for (int c = 0; c < 4; c++) { acc_sc[j][t][c] = 0.f; acc3[j][t][c] = 0.f; }

    // ---- shortcut: K = 240 in 6 chunks of 40 ----
    for (int kc = 0; kc < 6; kc++) {
        stage_B(x + ((size_t)n * CIN + kc * 40) * HW + tile * 64, tid);
        const uint4* wf = g_wscf + (size_t)(ct * 6 + kc) * 1600;
        for (int i = tid; i < 1600; i += 256) s_wf[i] = wf[i];
        __syncthreads();
        compute_chunk(wm, wn, lane, acc_sc);
        __syncthreads();
    }

    // ---- conv3: K = 40 (input already shuffled; group = ct) ----
    {
        stage_B(g_y2 + ((size_t)n * MID + ct * GMID) * HW + tile * 64, tid);
        const uint4* wf = g_w3f + (size_t)ct * 1600;
        for (int i = tid; i < 1600; i += 256) s_wf[i] = wf[i];
        __syncthreads();
        compute_chunk(wm, wn, lane, acc3);
    }

    // ---- epilogue: relu(BN3) + BN_sc, STG.64 px pairs ----
    #pragma unroll
    for (int j = 0; j < 5; j++) {
        int rb = ct * GOUT + wm * 80 + j * 16;
        int r0 = rb + gid, r1 = rb + gid + 8;
        float s3a = scale3[r0], h3a = shift3[r0], ssa = scale_sc[r0], hsa = shift_sc[r0];
        float s3b = scale3[r1], h3b = shift3[r1], ssb = scale_sc[r1], hsb = shift_sc[r1];
        #pragma unroll
        for (int t = 0; t < 2; t++) {
            int px = tile * 64 + wn * 16 + t * 8 + 2 * tig;
            float* o0 = out + ((size_t)n * COUT + r0) * HW + px;
            float* o1 = out + ((size_t)n * COUT + r1) * HW + px;
            float2 v0, v1;
            v0.x = fmaxf(fmaf(acc3[j][t][0], s3a, h3a), 0.f) + fmaf(acc_sc[j][t][0], ssa, hsa);
            v0.y = fmaxf(fmaf(acc3[j][t][1], s3a, h3a), 0.f) + fmaf(acc_sc[j][t][1], ssa, hsa);
            v1.x = fmaxf(fmaf(acc3[j][t][2], s3b, h3b), 0.f) + fmaf(acc_sc[j][t][2], ssb, hsb);
            v1.y = fmaxf(fmaf(acc3[j][t][3], s3b, h3b), 0.f) + fmaf(acc_sc[j][t][3], ssb, hsb);
            *reinterpret_cast<float2*>(o0) = v0;
            *reinterpret_cast<float2*>(o1) = v1;
        }
    }
}

// ---------------------------------------------------------------------------
extern "C" void kernel_launch(void* const* d_in, const int* in_sizes, int n_in,
                              void* d_out, int out_size)
{
    const float* x        = (const float*)d_in[0];
    const float* w1       = (const float*)d_in[1];
    const float* scale1   = (const float*)d_in[2];
    const float* shift1   = (const float*)d_in[3];
    const float* w2       = (const float*)d_in[4];
    const float* scale2   = (const float*)d_in[5];
    const float* shift2   = (const float*)d_in[6];
    const float* w3       = (const float*)d_in[7];
    const float* scale3   = (const float*)d_in[8];
    const float* shift3   = (const float*)d_in[9];
    const float* wsc      = (const float*)d_in[10];
    const float* scale_sc = (const float*)d_in[11];
    const float* shift_sc = (const float*)d_in[12];
    float* out = (float*)d_out;

    prep_w<<<(28800 + 4800 + 255) / 256, 256>>>(wsc, w3);
    k1_conv1<<<dim3(49, 3, 32), 256>>>(x, w1, scale1, shift1);
    k2_dw<<<dim3((NB * MID * HW) / 256), 256>>>(w2, scale2, shift2);
    k3_fused<<<dim3(49, 3, 32), 256>>>(x, scale3, shift3,
                                       scale_sc, shift_sc, out);
}

// round 3
// speedup vs baseline: 2.6845x; 2.3467x over previous
#include <cuda_runtime.h>

#define NB   32
#define CIN  240
#define HH   56
#define WW   56
#define HW   3136
#define MID  120
#define COUT 480
#define GRP  3
#define GIN  80    // Cin / G
#define GMID 40    // mid / G
#define GOUT 160   // Cout / G

// Scratch (allocation-free rule: __device__ globals)
__device__ float g_y1[NB * MID * HW];   // conv1 output (post BN+ReLU)
__device__ float g_y2[NB * MID * HW];   // dw output, SHUFFLED channel order
// Pre-packed tf32 A-fragments (mma.m16n8k8 per-lane layout), BN scale FOLDED IN
// wsc*scale_sc: [ct(3)][kc(6)][kq(5)][mt(10)][lane(32)] -> 28800 uint4
// w3 *scale3  : [ct(3)][kq(5)][mt(10)][lane(32)]        -> 4800 uint4
__device__ uint4 g_wscf[28800];
__device__ uint4 g_w3f[4800];

static __device__ __forceinline__ unsigned cvt_tf32(float f) {
    unsigned u; asm("cvt.rna.tf32.f32 %0, %1;" : "=r"(u) : "f"(f)); return u;
}

static __device__ __forceinline__ void mma_tf32(float c[4], const unsigned a[4],
                                                const unsigned b[2]) {
    asm volatile(
        "mma.sync.aligned.m16n8k8.row.col.f32.tf32.tf32.f32 "
        "{%0,%1,%2,%3}, {%4,%5,%6,%7}, {%8,%9}, {%0,%1,%2,%3};"
        : "+f"(c[0]), "+f"(c[1]), "+f"(c[2]), "+f"(c[3])
        : "r"(a[0]), "r"(a[1]), "r"(a[2]), "r"(a[3]), "r"(b[0]), "r"(b[1]));
}

// ---------------------------------------------------------------------------
// prep: repack wsc/w3 into per-lane tf32 A-fragments with BN scales folded in.
// ---------------------------------------------------------------------------
__global__ void prep_w(const float* __restrict__ wsc, const float* __restrict__ w3,
                       const float* __restrict__ scale_sc, const float* __restrict__ scale3)
{
    int idx = blockIdx.x * 256 + threadIdx.x;
    if (idx < 28800) {
        int lane = idx & 31; int r = idx >> 5;
        int mt = r % 10; r /= 10;
        int kq = r % 5;  r /= 5;
        int kc = r % 6;  int ct = r / 6;
        int gid = lane >> 2, tig = lane & 3;
        int row = ct * GOUT + mt * 16 + gid;
        int col = kc * 40 + kq * 8 + tig;
        float sa = scale_sc[row], sb = scale_sc[row + 8];
        uint4 v;
        v.x = cvt_tf32(wsc[row * CIN + col] * sa);
        v.y = cvt_tf32(wsc[(row + 8) * CIN + col] * sb);
        v.z = cvt_tf32(wsc[row * CIN + col + 4] * sa);
        v.w = cvt_tf32(wsc[(row + 8) * CIN + col + 4] * sb);
        g_wscf[idx] = v;
    } else if (idx < 28800 + 4800) {
        int i2 = idx - 28800;
        int lane = i2 & 31; int r = i2 >> 5;
        int mt = r % 10; r /= 10;
        int kq = r % 5;  int ct = r / 5;
        int gid = lane >> 2, tig = lane & 3;
        int row = ct * GOUT + mt * 16 + gid;
        int col = kq * 8 + tig;
        float sa = scale3[row], sb = scale3[row + 8];
        uint4 v;
        v.x = cvt_tf32(w3[row * GMID + col] * sa);
        v.y = cvt_tf32(w3[(row + 8) * GMID + col] * sb);
        v.z = cvt_tf32(w3[row * GMID + col + 4] * sa);
        v.w = cvt_tf32(w3[(row + 8) * GMID + col + 4] * sb);
        g_w3f[i2] = v;
    }
}

// ---------------------------------------------------------------------------
// K1: grouped 1x1 conv + BN + ReLU -> g_y1 (fp32 scalar)
// ---------------------------------------------------------------------------
__global__ __launch_bounds__(256) void k1_conv1(
    const float* __restrict__ x, const float* __restrict__ w1,
    const float* __restrict__ scale1, const float* __restrict__ shift1)
{
    const int tile = blockIdx.x, g = blockIdx.y, n = blockIdx.z;
    const int tid = threadIdx.x, lane = tid & 31, warp = tid >> 5;
    const int wm4 = warp & 3;        // m block of 10
    const int wp  = warp >> 2;       // pixel half

    __shared__ float xs[GIN][64];
    __shared__ float wt2[GIN][48];

    const float4* x4 = reinterpret_cast<const float4*>(
        x + ((size_t)n * CIN + g * GIN) * HW + tile * 64);
    for (int i = tid; i < GIN * 16; i += 256) {
        int c = i >> 4, q = i & 15;
        reinterpret_cast<float4*>(xs[c])[q] = x4[c * (HW / 4) + q];
    }
    for (int i = tid; i < GIN * GMID; i += 256) {
        int k = i % GIN, mi = i / GIN;
        wt2[k][(mi / 10) * 12 + (mi % 10)] = w1[(g * GMID + mi) * GIN + k];
    }
    __syncthreads();

    float acc[10] = {};
    #pragma unroll 2
    for (int k = 0; k < GIN; k++) {
        float b = xs[k][wp * 32 + lane];
        const float* wr = &wt2[k][wm4 * 12];
        float4 wa = *reinterpret_cast<const float4*>(wr);
        float4 wb = *reinterpret_cast<const float4*>(wr + 4);
        float2 wc = *reinterpret_cast<const float2*>(wr + 8);
        acc[0] = fmaf(wa.x, b, acc[0]); acc[1] = fmaf(wa.y, b, acc[1]);
        acc[2] = fmaf(wa.z, b, acc[2]); acc[3] = fmaf(wa.w, b, acc[3]);
        acc[4] = fmaf(wb.x, b, acc[4]); acc[5] = fmaf(wb.y, b, acc[5]);
        acc[6] = fmaf(wb.z, b, acc[6]); acc[7] = fmaf(wb.w, b, acc[7]);
        acc[8] = fmaf(wc.x, b, acc[8]); acc[9] = fmaf(wc.y, b, acc[9]);
    }

    float* yp = g_y1 + (size_t)n * MID * HW + tile * 64 + wp * 32 + lane;
    #pragma unroll
    for (int j = 0; j < 10; j++) {
        int mg = g * GMID + wm4 * 10 + j;
        yp[(size_t)mg * HW] = fmaxf(fmaf(acc[j], scale1[mg], shift1[mg]), 0.f);
    }
}

// ---------------------------------------------------------------------------
// K2: depthwise 3x3 (pad 1) + BN, channel-shuffled write -> g_y2
// ---------------------------------------------------------------------------
__global__ __launch_bounds__(256) void k2_dw(
    const float* __restrict__ w2, const float* __restrict__ scale2,
    const float* __restrict__ shift2)
{
    int idx = blockIdx.x * 256 + threadIdx.x;
    int hw = idx % HW, nm = idx / HW;
    int m = nm % MID, n = nm / MID;
    int h = hw / WW, w = hw % WW;

    const float* yp = g_y1 + (size_t)nm * HW;
    const float* wp = w2 + m * 9;
    float acc = 0.f;
    #pragma unroll
    for (int dh = -1; dh <= 1; dh++) {
        int h2 = h + dh;
        if (h2 < 0 || h2 >= HH) continue;
        #pragma unroll
        for (int dw = -1; dw <= 1; dw++) {
            int w2i = w + dw;
            if (w2i < 0 || w2i >= WW) continue;
            acc = fmaf(wp[(dh + 1) * 3 + (dw + 1)], yp[h2 * WW + w2i], acc);
        }
    }
    float v = fmaf(acc, scale2[m], shift2[m]);
    int s = (m % GMID) * GRP + m / GMID;
    g_y2[((size_t)n * MID + s) * HW + hw] = v;
}

// ---------------------------------------------------------------------------
// K3: tf32 MMA, single accumulator (scales folded), A-frags via direct LDG
// (software-pipelined), B tile double-buffered in smem, 2 CTAs/SM.
// chunk 0 = conv3 (K=40, g_y2) -> in-register relu transform -> chunks 1..6 =
// shortcut (K=240). grid (49, 3, 32), 256 thr.
// ---------------------------------------------------------------------------
#define BSTR 33
#define BSZ  (5 * 8 * BSTR)   // 1320

struct BReg { float4 v0, v1, v2; };

static __device__ __forceinline__ void ldg_B(const float* __restrict__ src,
                                             int tid, BReg& r)
{
    const float4* s4 = reinterpret_cast<const float4*>(src);
    r.v0 = s4[(tid >> 4) * (HW / 4) + (tid & 15)];
    int i1 = tid + 256;
    r.v1 = s4[(i1 >> 4) * (HW / 4) + (i1 & 15)];
    if (tid < 128) {
        int i2 = tid + 512;
        r.v2 = s4[(i2 >> 4) * (HW / 4) + (i2 & 15)];
    }
}

static __device__ __forceinline__ void sts_one(unsigned* __restrict__ b0,
                                               unsigned* __restrict__ b1,
                                               int i, float4 v)
{
    int c = i >> 4, q = i & 15;
    int kq = c >> 3, tig = c & 3;
    unsigned* dst = ((c >> 2) & 1) ? b1 : b0;
    int p0 = 4 * q;
    dst[(kq * 8 + ((p0    ) >> 3)) * BSTR + ((p0    ) & 7) * 4 + tig] = cvt_tf32(v.x);
    dst[(kq * 8 + ((p0 + 1) >> 3)) * BSTR + ((p0 + 1) & 7) * 4 + tig] = cvt_tf32(v.y);
    dst[(kq * 8 + ((p0 + 2) >> 3)) * BSTR + ((p0 + 2) & 7) * 4 + tig] = cvt_tf32(v.z);
    dst[(kq * 8 + ((p0 + 3) >> 3)) * BSTR + ((p0 + 3) & 7) * 4 + tig] = cvt_tf32(v.w);
}

static __device__ __forceinline__ void sts_B(unsigned* __restrict__ b0,
                                             unsigned* __restrict__ b1,
                                             int tid, const BReg& r)
{
    sts_one(b0, b1, tid, r.v0);
    sts_one(b0, b1, tid + 256, r.v1);
    if (tid < 128) sts_one(b0, b1, tid + 512, r.v2);
}

static __device__ __forceinline__ void compute_chunk(
    const uint4* __restrict__ wf,
    const unsigned* __restrict__ b0, const unsigned* __restrict__ b1,
    int wm, int wn, int lane, float acc[5][2][4])
{
    unsigned a_cur[5][4], a_nxt[5][4];
    #pragma unroll
    for (int j = 0; j < 5; j++)
        *reinterpret_cast<uint4*>(a_cur[j]) = wf[(wm * 5 + j) * 32 + lane];
    #pragma unroll
    for (int kq = 0; kq < 5; kq++) {
        if (kq < 4) {
            #pragma unroll
            for (int j = 0; j < 5; j++)
                *reinterpret_cast<uint4*>(a_nxt[j]) =
                    wf[((kq + 1) * 10 + wm * 5 + j) * 32 + lane];
        }
        unsigned b[2][2];
        #pragma unroll
        for (int t = 0; t < 2; t++) {
            int bi = (kq * 8 + wn * 2 + t) * BSTR + lane;
            b[t][0] = b0[bi];
            b[t][1] = b1[bi];
        }
        #pragma unroll
        for (int j = 0; j < 5; j++)
            #pragma unroll
            for (int t = 0; t < 2; t++)
                mma_tf32(acc[j][t], a_cur[j], b[t]);
        if (kq < 4) {
            #pragma unroll
            for (int j = 0; j < 5; j++)
                #pragma unroll
                for (int c = 0; c < 4; c++) a_cur[j][c] = a_nxt[j][c];
        }
    }
}

__global__ __launch_bounds__(256, 2) void k3_fused(
    const float* __restrict__ x,
    const float* __restrict__ shift3, const float* __restrict__ shift_sc,
    float* __restrict__ out)
{
    const int tile = blockIdx.x, ct = blockIdx.y, n = blockIdx.z;
    const int tid = threadIdx.x, lane = tid & 31, warp = tid >> 5;
    const int wm = warp & 1;           // m half (80 rows)
    const int wn = warp >> 1;          // 16-px strip
    const int gid = lane >> 2, tig = lane & 3;

    __shared__ unsigned s_b0[2][BSZ];
    __shared__ unsigned s_b1[2][BSZ];

    float acc[5][2][4];
    #pragma unroll
    for (int j = 0; j < 5; j++)
        #pragma unroll
        for (int t = 0; t < 2; t++)
            #pragma unroll
            for (int c = 0; c < 4; c++) acc[j][t][c] = 0.f;

    BReg br;

    // prologue: stage conv3 B tile (chunk 0 -> buf0)
    ldg_B(g_y2 + ((size_t)n * MID + ct * GMID) * HW + tile * 64, tid, br);
    sts_B(s_b0[0], s_b1[0], tid, br);
    __syncthreads();

    // chunk 0: conv3 (weights pre-scaled by scale3); prefetch chunk 1 B
    ldg_B(x + ((size_t)n * CIN + 0) * HW + tile * 64, tid, br);
    compute_chunk(g_w3f + (size_t)ct * 1600, s_b0[0], s_b1[0], wm, wn, lane, acc);
    sts_B(s_b0[1], s_b1[1], tid, br);

    // in-register transform: acc := relu(acc + shift3) + shift_sc
    #pragma unroll
    for (int j = 0; j < 5; j++) {
        int rb = ct * GOUT + wm * 80 + j * 16;
        int r0 = rb + gid, r1 = r0 + 8;
        float h3a = shift3[r0], hsa = shift_sc[r0];
        float h3b = shift3[r1], hsb = shift_sc[r1];
        #pragma unroll
        for (int t = 0; t < 2; t++) {
            acc[j][t][0] = fmaxf(acc[j][t][0] + h3a, 0.f) + hsa;
            acc[j][t][1] = fmaxf(acc[j][t][1] + h3a, 0.f) + hsa;
            acc[j][t][2] = fmaxf(acc[j][t][2] + h3b, 0.f) + hsb;
            acc[j][t][3] = fmaxf(acc[j][t][3] + h3b, 0.f) + hsb;
        }
    }
    __syncthreads();

    // chunks 1..6: shortcut (weights pre-scaled by scale_sc), MMA accumulates
    // on top of the transformed value.
    #pragma unroll 1
    for (int kc = 0; kc < 6; kc++) {
        if (kc < 5)
            ldg_B(x + ((size_t)n * CIN + (kc + 1) * 40) * HW + tile * 64, tid, br);
        int cb = (kc + 1) & 1;     // buffer holding chunk kc+1's data
        compute_chunk(g_wscf + (size_t)(ct * 6 + kc) * 1600,
                      s_b0[cb], s_b1[cb], wm, wn, lane, acc);
        if (kc < 5) {
            sts_B(s_b0[kc & 1], s_b1[kc & 1], tid, br);
            __syncthreads();
        }
    }

    // epilogue: store (shift terms already applied)
    #pragma unroll
    for (int j = 0; j < 5; j++) {
        int rb = ct * GOUT + wm * 80 + j * 16;
        int r0 = rb + gid, r1 = r0 + 8;
        #pragma unroll
        for (int t = 0; t < 2; t++) {
            int px = tile * 64 + wn * 16 + t * 8 + 2 * tig;
            float2 v0, v1;
            v0.x = acc[j][t][0]; v0.y = acc[j][t][1];
            v1.x = acc[j][t][2]; v1.y = acc[j][t][3];
            *reinterpret_cast<float2*>(out + ((size_t)n * COUT + r0) * HW + px) = v0;
            *reinterpret_cast<float2*>(out + ((size_t)n * COUT + r1) * HW + px) = v1;
        }
    }
}

// ---------------------------------------------------------------------------
extern "C" void kernel_launch(void* const* d_in, const int* in_sizes, int n_in,
                              void* d_out, int out_size)
{
    const float* x        = (const float*)d_in[0];
    const float* w1       = (const float*)d_in[1];
    const float* scale1   = (const float*)d_in[2];
    const float* shift1   = (const float*)d_in[3];
    const float* w2       = (const float*)d_in[4];
    const float* scale2   = (const float*)d_in[5];
    const float* shift2   = (const float*)d_in[6];
    const float* w3       = (const float*)d_in[7];
    const float* scale3   = (const float*)d_in[8];
    const float* shift3   = (const float*)d_in[9];
    const float* wsc      = (const float*)d_in[10];
    const float* scale_sc = (const float*)d_in[11];
    const float* shift_sc = (const float*)d_in[12];
    float* out = (float*)d_out;

    prep_w<<<(28800 + 4800 + 255) / 256, 256>>>(wsc, w3, scale_sc, scale3);
    k1_conv1<<<dim3(49, 3, 32), 256>>>(x, w1, scale1, shift1);
    k2_dw<<<dim3((NB * MID * HW) / 256), 256>>>(w2, scale2, shift2);
    k3_fused<<<dim3(49, 3, 32), 256>>>(x, shift3, shift_sc, out);
}

// round 4
// speedup vs baseline: 3.1064x; 1.1572x over previous
#include <cuda_runtime.h>

#define NB   32
#define CIN  240
#define HH   56
#define WW   56
#define HW   3136
#define MID  120
#define COUT 480
#define GRP  3
#define GIN  80    // Cin / G
#define GMID 40    // mid / G
#define GOUT 160   // Cout / G

// Scratch (allocation-free rule: __device__ globals)
__device__ float g_y1[NB * MID * HW];   // conv1 output (post BN+ReLU)
__device__ float g_y2[NB * MID * HW];   // dw output, SHUFFLED channel order
// Pre-packed tf32 A-fragments (mma.m16n8k8 per-lane layout), BN scale FOLDED IN
__device__ uint4 g_wscf[28800];
__device__ uint4 g_w3f[4800];

static __device__ __forceinline__ unsigned cvt_tf32(float f) {
    unsigned u; asm("cvt.rna.tf32.f32 %0, %1;" : "=r"(u) : "f"(f)); return u;
}

static __device__ __forceinline__ void mma_tf32(float c[4], const unsigned a[4],
                                                const unsigned b[2]) {
    asm volatile(
        "mma.sync.aligned.m16n8k8.row.col.f32.tf32.tf32.f32 "
        "{%0,%1,%2,%3}, {%4,%5,%6,%7}, {%8,%9}, {%0,%1,%2,%3};"
        : "+f"(c[0]), "+f"(c[1]), "+f"(c[2]), "+f"(c[3])
        : "r"(a[0]), "r"(a[1]), "r"(a[2]), "r"(a[3]), "r"(b[0]), "r"(b[1]));
}

static __device__ __forceinline__ unsigned smem_u32(const void* p) {
    return (unsigned)__cvta_generic_to_shared(p);
}
#define CP16(dst, src) \
    asm volatile("cp.async.cg.shared.global [%0], [%1], 16;" :: "r"(dst), "l"(src))
#define CP_COMMIT() asm volatile("cp.async.commit_group;")
#define CP_WAIT0()  asm volatile("cp.async.wait_group 0;")

// ---------------------------------------------------------------------------
// prep: repack wsc/w3 into per-lane tf32 A-fragments with BN scales folded in.
// ---------------------------------------------------------------------------
__global__ void prep_w(const float* __restrict__ wsc, const float* __restrict__ w3,
                       const float* __restrict__ scale_sc, const float* __restrict__ scale3)
{
    int idx = blockIdx.x * 256 + threadIdx.x;
    if (idx < 28800) {
        int lane = idx & 31; int r = idx >> 5;
        int mt = r % 10; r /= 10;
        int kq = r % 5;  r /= 5;
        int kc = r % 6;  int ct = r / 6;
        int gid = lane >> 2, tig = lane & 3;
        int row = ct * GOUT + mt * 16 + gid;
        int col = kc * 40 + kq * 8 + tig;
        float sa = scale_sc[row], sb = scale_sc[row + 8];
        uint4 v;
        v.x = cvt_tf32(wsc[row * CIN + col] * sa);
        v.y = cvt_tf32(wsc[(row + 8) * CIN + col] * sb);
        v.z = cvt_tf32(wsc[row * CIN + col + 4] * sa);
        v.w = cvt_tf32(wsc[(row + 8) * CIN + col + 4] * sb);
        g_wscf[idx] = v;
    } else if (idx < 28800 + 4800) {
        int i2 = idx - 28800;
        int lane = i2 & 31; int r = i2 >> 5;
        int mt = r % 10; r /= 10;
        int kq = r % 5;  int ct = r / 5;
        int gid = lane >> 2, tig = lane & 3;
        int row = ct * GOUT + mt * 16 + gid;
        int col = kq * 8 + tig;
        float sa = scale3[row], sb = scale3[row + 8];
        uint4 v;
        v.x = cvt_tf32(w3[row * GMID + col] * sa);
        v.y = cvt_tf32(w3[(row + 8) * GMID + col] * sb);
        v.z = cvt_tf32(w3[row * GMID + col + 4] * sa);
        v.w = cvt_tf32(w3[(row + 8) * GMID + col + 4] * sb);
        g_w3f[i2] = v;
    }
}

// ---------------------------------------------------------------------------
// K1: grouped 1x1 conv + BN + ReLU -> g_y1 (fp32 scalar)
// ---------------------------------------------------------------------------
__global__ __launch_bounds__(256) void k1_conv1(
    const float* __restrict__ x, const float* __restrict__ w1,
    const float* __restrict__ scale1, const float* __restrict__ shift1)
{
    const int tile = blockIdx.x, g = blockIdx.y, n = blockIdx.z;
    const int tid = threadIdx.x, lane = tid & 31, warp = tid >> 5;
    const int wm4 = warp & 3;
    const int wp  = warp >> 2;

    __shared__ float xs[GIN][64];
    __shared__ float wt2[GIN][48];

    const float4* x4 = reinterpret_cast<const float4*>(
        x + ((size_t)n * CIN + g * GIN) * HW + tile * 64);
    for (int i = tid; i < GIN * 16; i += 256) {
        int c = i >> 4, q = i & 15;
        reinterpret_cast<float4*>(xs[c])[q] = x4[c * (HW / 4) + q];
    }
    for (int i = tid; i < GIN * GMID; i += 256) {
        int k = i % GIN, mi = i / GIN;
        wt2[k][(mi / 10) * 12 + (mi % 10)] = w1[(g * GMID + mi) * GIN + k];
    }
    __syncthreads();

    float acc[10] = {};
    #pragma unroll 2
    for (int k = 0; k < GIN; k++) {
        float b = xs[k][wp * 32 + lane];
        const float* wr = &wt2[k][wm4 * 12];
        float4 wa = *reinterpret_cast<const float4*>(wr);
        float4 wb = *reinterpret_cast<const float4*>(wr + 4);
        float2 wc = *reinterpret_cast<const float2*>(wr + 8);
        acc[0] = fmaf(wa.x, b, acc[0]); acc[1] = fmaf(wa.y, b, acc[1]);
        acc[2] = fmaf(wa.z, b, acc[2]); acc[3] = fmaf(wa.w, b, acc[3]);
        acc[4] = fmaf(wb.x, b, acc[4]); acc[5] = fmaf(wb.y, b, acc[5]);
        acc[6] = fmaf(wb.z, b, acc[6]); acc[7] = fmaf(wb.w, b, acc[7]);
        acc[8] = fmaf(wc.x, b, acc[8]); acc[9] = fmaf(wc.y, b, acc[9]);
    }

    float* yp = g_y1 + (size_t)n * MID * HW + tile * 64 + wp * 32 + lane;
    #pragma unroll
    for (int j = 0; j < 10; j++) {
        int mg = g * GMID + wm4 * 10 + j;
        yp[(size_t)mg * HW] = fmaxf(fmaf(acc[j], scale1[mg], shift1[mg]), 0.f);
    }
}

// ---------------------------------------------------------------------------
// K2: depthwise 3x3 (pad 1) + BN, channel-shuffled write -> g_y2
// 4 outputs per thread along w (float4 I/O): 9 loads / 4 outputs.
// ---------------------------------------------------------------------------
__global__ __launch_bounds__(256) void k2_dw(
    const float* __restrict__ w2, const float* __restrict__ scale2,
    const float* __restrict__ shift2)
{
    int idx = blockIdx.x * 256 + threadIdx.x;   // NB*MID*784 threads exactly
    int q  = idx % 784;
    int nm = idx / 784;
    int m  = nm % MID, n = nm / MID;
    int w0 = (q * 4) % WW, h = (q * 4) / WW;

    const float* p = g_y1 + (size_t)nm * HW + h * WW + w0;
    float l[3][6];
    #pragma unroll
    for (int r = 0; r < 3; r++) {
        int hh = h - 1 + r;
        if (hh >= 0 && hh < HH) {
            const float* pr = p + (r - 1) * WW;
            float4 c4 = *reinterpret_cast<const float4*>(pr);
            l[r][1] = c4.x; l[r][2] = c4.y; l[r][3] = c4.z; l[r][4] = c4.w;
            l[r][0] = (w0 > 0)       ? pr[-1] : 0.f;
            l[r][5] = (w0 + 4 < WW)  ? pr[4]  : 0.f;
        } else {
            #pragma unroll
            for (int j = 0; j < 6; j++) l[r][j] = 0.f;
        }
    }

    const float* wp = w2 + m * 9;
    float wgt[9];
    #pragma unroll
    for (int i = 0; i < 9; i++) wgt[i] = wp[i];

    float s = scale2[m], sh = shift2[m];
    float4 o;
    float* oj = &o.x;
    #pragma unroll
    for (int j = 0; j < 4; j++) {
        float a = 0.f;
        #pragma unroll
        for (int r = 0; r < 3; r++)
            #pragma unroll
            for (int d = 0; d < 3; d++)
                a = fmaf(wgt[r * 3 + d], l[r][j + d], a);
        oj[j] = fmaf(a, s, sh);
    }

    int sc = (m % GMID) * GRP + m / GMID;       // channel shuffle
    *reinterpret_cast<float4*>(g_y2 + ((size_t)n * MID + sc) * HW + h * WW + w0) = o;
}

// ---------------------------------------------------------------------------
// K3: tf32 MMA; A-fragments prefetched a full chunk ahead via cp.async (smem
// double buffer, L1-bypassing), B tile register-pipelined as before.
// grid (49, 3, 32), 256 thr, 2 CTAs/SM, dynamic smem 72320 B.
// ---------------------------------------------------------------------------
#define BSTR 33
#define BSZ  (5 * 8 * BSTR)   // 1320
#define AW_ELEMS 1600
#define SMEM_K3 (2 * AW_ELEMS * 16 + 2 * BSZ * 4 * 2)   // 51200 + 21120 = 72320

struct BReg { float4 v0, v1, v2; };

static __device__ __forceinline__ void ldg_B(const float* __restrict__ src,
                                             int tid, BReg& r)
{
    const float4* s4 = reinterpret_cast<const float4*>(src);
    r.v0 = s4[(tid >> 4) * (HW / 4) + (tid & 15)];
    int i1 = tid + 256;
    r.v1 = s4[(i1 >> 4) * (HW / 4) + (i1 & 15)];
    if (tid < 128) {
        int i2 = tid + 512;
        r.v2 = s4[(i2 >> 4) * (HW / 4) + (i2 & 15)];
    }
}

static __device__ __forceinline__ void sts_one(unsigned* __restrict__ b0,
                                               unsigned* __restrict__ b1,
                                               int i, float4 v)
{
    int c = i >> 4, q = i & 15;
    int kq = c >> 3, tig = c & 3;
    unsigned* dst = ((c >> 2) & 1) ? b1 : b0;
    int p0 = 4 * q;
    dst[(kq * 8 + ((p0    ) >> 3)) * BSTR + ((p0    ) & 7) * 4 + tig] = cvt_tf32(v.x);
    dst[(kq * 8 + ((p0 + 1) >> 3)) * BSTR + ((p0 + 1) & 7) * 4 + tig] = cvt_tf32(v.y);
    dst[(kq * 8 + ((p0 + 2) >> 3)) * BSTR + ((p0 + 2) & 7) * 4 + tig] = cvt_tf32(v.z);
    dst[(kq * 8 + ((p0 + 3) >> 3)) * BSTR + ((p0 + 3) & 7) * 4 + tig] = cvt_tf32(v.w);
}

static __device__ __forceinline__ void sts_B(unsigned* __restrict__ b0,
                                             unsigned* __restrict__ b1,
                                             int tid, const BReg& r)
{
    sts_one(b0, b1, tid, r.v0);
    sts_one(b0, b1, tid + 256, r.v1);
    if (tid < 128) sts_one(b0, b1, tid + 512, r.v2);
}

static __device__ __forceinline__ void cp_A(uint4* __restrict__ dst,
                                            const uint4* __restrict__ src, int tid)
{
    unsigned d = smem_u32(dst);
    #pragma unroll 2
    for (int i = tid; i < AW_ELEMS; i += 256)
        CP16(d + i * 16, src + i);
}

static __device__ __forceinline__ void compute_chunk(
    const uint4* __restrict__ aw,
    const unsigned* __restrict__ b0, const unsigned* __restrict__ b1,
    int wm, int wn, int lane, float acc[5][2][4])
{
    #pragma unroll
    for (int kq = 0; kq < 5; kq++) {
        unsigned a[5][4];
        #pragma unroll
        for (int j = 0; j < 5; j++)
            *reinterpret_cast<uint4*>(a[j]) = aw[(kq * 10 + wm * 5 + j) * 32 + lane];
        unsigned b[2][2];
        #pragma unroll
        for (int t = 0; t < 2; t++) {
            int bi = (kq * 8 + wn * 2 + t) * BSTR + lane;
            b[t][0] = b0[bi];
            b[t][1] = b1[bi];
        }
        #pragma unroll
        for (int j = 0; j < 5; j++)
            #pragma unroll
            for (int t = 0; t < 2; t++)
                mma_tf32(acc[j][t], a[j], b[t]);
    }
}

__global__ __launch_bounds__(256, 2) void k3_fused(
    const float* __restrict__ x,
    const float* __restrict__ shift3, const float* __restrict__ shift_sc,
    float* __restrict__ out)
{
    const int tile = blockIdx.x, ct = blockIdx.y, n = blockIdx.z;
    const int tid = threadIdx.x, lane = tid & 31, warp = tid >> 5;
    const int wm = warp & 1;
    const int wn = warp >> 1;
    const int gid = lane >> 2, tig = lane & 3;

    extern __shared__ __align__(16) char smem[];
    uint4*    s_aw = reinterpret_cast<uint4*>(smem);                       // [2][1600]
    unsigned* s_b0 = reinterpret_cast<unsigned*>(smem + 2 * AW_ELEMS * 16);        // [2][BSZ]
    unsigned* s_b1 = s_b0 + 2 * BSZ;                                               // [2][BSZ]

    float acc[5][2][4];
    #pragma unroll
    for (int j = 0; j < 5; j++)
        #pragma unroll
        for (int t = 0; t < 2; t++)
            #pragma unroll
            for (int c = 0; c < 4; c++) acc[j][t][c] = 0.f;

    // chunk sources: 0 = conv3 (A=g_w3f, B=g_y2), 1..6 = shortcut kc=c-1
    const uint4* a_src[7];
    a_src[0] = g_w3f + (size_t)ct * 1600;
    #pragma unroll
    for (int kc = 0; kc < 6; kc++) a_src[1 + kc] = g_wscf + (size_t)(ct * 6 + kc) * 1600;

    BReg br;

    // prologue
    cp_A(s_aw, a_src[0], tid);
    CP_COMMIT();
    ldg_B(g_y2 + ((size_t)n * MID + ct * GMID) * HW + tile * 64, tid, br);

    #pragma unroll 1
    for (int c = 0; c < 7; c++) {
        int cb = c & 1;
        sts_B(s_b0 + cb * BSZ, s_b1 + cb * BSZ, tid, br);
        CP_WAIT0();
        __syncthreads();
        if (c < 6) {
            cp_A(s_aw + ((c + 1) & 1) * AW_ELEMS, a_src[c + 1], tid);
            CP_COMMIT();
            ldg_B(x + ((size_t)n * CIN + c * 40) * HW + tile * 64, tid, br);
        }
        compute_chunk(s_aw + cb * AW_ELEMS, s_b0 + cb * BSZ, s_b1 + cb * BSZ,
                      wm, wn, lane, acc);
        if (c == 0) {
            // acc := relu(acc + shift3) + shift_sc ; shortcut chunks accumulate on top
            #pragma unroll
            for (int j = 0; j < 5; j++) {
                int rb = ct * GOUT + wm * 80 + j * 16;
                int r0 = rb + gid, r1 = r0 + 8;
                float h3a = shift3[r0], hsa = shift_sc[r0];
                float h3b = shift3[r1], hsb = shift_sc[r1];
                #pragma unroll
                for (int t = 0; t < 2; t++) {
                    acc[j][t][0] = fmaxf(acc[j][t][0] + h3a, 0.f) + hsa;
                    acc[j][t][1] = fmaxf(acc[j][t][1] + h3a, 0.f) + hsa;
                    acc[j][t][2] = fmaxf(acc[j][t][2] + h3b, 0.f) + hsb;
                    acc[j][t][3] = fmaxf(acc[j][t][3] + h3b, 0.f) + hsb;
                }
            }
        }
    }

    // epilogue
    #pragma unroll
    for (int j = 0; j < 5; j++) {
        int rb = ct * GOUT + wm * 80 + j * 16;
        int r0 = rb + gid, r1 = r0 + 8;
        #pragma unroll
        for (int t = 0; t < 2; t++) {
            int px = tile * 64 + wn * 16 + t * 8 + 2 * tig;
            float2 v0, v1;
            v0.x = acc[j][t][0]; v0.y = acc[j][t][1];
            v1.x = acc[j][t][2]; v1.y = acc[j][t][3];
            *reinterpret_cast<float2*>(out + ((size_t)n * COUT + r0) * HW + px) = v0;
            *reinterpret_cast<float2*>(out + ((size_t)n * COUT + r1) * HW + px) = v1;
        }
    }
}

// ---------------------------------------------------------------------------
extern "C" void kernel_launch(void* const* d_in, const int* in_sizes, int n_in,
                              void* d_out, int out_size)
{
    const float* x        = (const float*)d_in[0];
    const float* w1       = (const float*)d_in[1];
    const float* scale1   = (const float*)d_in[2];
    const float* shift1   = (const float*)d_in[3];
    const float* w2       = (const float*)d_in[4];
    const float* scale2   = (const float*)d_in[5];
    const float* shift2   = (const float*)d_in[6];
    const float* w3       = (const float*)d_in[7];
    const float* scale3   = (const float*)d_in[8];
    const float* shift3   = (const float*)d_in[9];
    const float* wsc      = (const float*)d_in[10];
    const float* scale_sc = (const float*)d_in[11];
    const float* shift_sc = (const float*)d_in[12];
    float* out = (float*)d_out;

    cudaFuncSetAttribute(k3_fused, cudaFuncAttributeMaxDynamicSharedMemorySize, SMEM_K3);

    prep_w<<<(28800 + 4800 + 255) / 256, 256>>>(wsc, w3, scale_sc, scale3);
    k1_conv1<<<dim3(49, 3, 32), 256>>>(x, w1, scale1, shift1);
    k2_dw<<<dim3((NB * MID * 784) / 256), 256>>>(w2, scale2, shift2);
    k3_fused<<<dim3(49, 3, 32), 256, SMEM_K3>>>(x, shift3, shift_sc, out);
}